// round 16
// baseline (speedup 1.0000x reference)
#include <cuda_runtime.h>
#include <cuda_fp16.h>
#include <cstdint>

#define BATCH 8
#define SEQ   512
#define DIM   768
#define HEADS 12
#define DHEAD 64
#define ROWS  (BATCH * SEQ)        // 4096
#define MAT   (ROWS * DIM)         // 3145728
#define W768  (768 * 768)
#define W1536 (1536 * 768)

__device__ float g_scratch[17ULL * MAT];

__device__ __forceinline__ uint32_t packf16(float lo, float hi) {
    uint32_t r;
    asm("cvt.rn.f16x2.f32 %0, %1, %2;" : "=r"(r) : "f"(hi), "f"(lo));
    return r;
}

#define MMA_F16(D, A, B0, B1)                                               \
    asm volatile(                                                           \
        "mma.sync.aligned.m16n8k16.row.col.f32.f16.f16.f32 "                \
        "{%0,%1,%2,%3}, {%4,%5,%6,%7}, {%8,%9}, {%0,%1,%2,%3};"             \
        : "+f"((D)[0]), "+f"((D)[1]), "+f"((D)[2]), "+f"((D)[3])            \
        : "r"((A)[0]), "r"((A)[1]), "r"((A)[2]), "r"((A)[3]),               \
          "r"(B0), "r"(B1))

#define LDSM_X4(R0, R1, R2, R3, ADDR)                                       \
    asm volatile("ldmatrix.sync.aligned.m8n8.x4.shared.b16 {%0,%1,%2,%3}, [%4];" \
        : "=r"(R0), "=r"(R1), "=r"(R2), "=r"(R3) : "r"(ADDR))

#define CP_COMMIT() asm volatile("cp.async.commit_group;")

__device__ __forceinline__ void cp16(void* smem_ptr, const void* gptr) {
    uint32_t saddr = (uint32_t)__cvta_generic_to_shared(smem_ptr);
    asm volatile("cp.async.ca.shared.global [%0], [%1], 16;" :: "r"(saddr), "l"(gptr));
}

// ---------------------------------------------------------------------------
// Pre-pass 1: transpose weights to [N,K] fp16
// ---------------------------------------------------------------------------
struct TJ { const float* src; __half* dst; int K; int N; };
struct TBatch { TJ j[10]; };

__global__ __launch_bounds__(256) void transpose_round(TBatch tb)
{
    __shared__ float t[32][33];
    const TJ J = tb.j[blockIdx.z];
    int k0 = blockIdx.x * 32, n0 = blockIdx.y * 32;
    if (k0 >= J.K || n0 >= J.N) return;
    int tx = threadIdx.x & 31, ty = threadIdx.x >> 5;
    #pragma unroll
    for (int i = 0; i < 4; i++)
        t[ty + i * 8][tx] = J.src[(size_t)(k0 + ty + i * 8) * J.N + n0 + tx];
    __syncthreads();
    #pragma unroll
    for (int i = 0; i < 4; i++)
        J.dst[(size_t)(n0 + ty + i * 8) * J.K + k0 + tx] =
            __float2half(t[tx][ty + i * 8]);
}

// Pre-pass 2: fp32 -> fp16 copies of hs, mol
__global__ __launch_bounds__(256) void round_copy(const float* __restrict__ a,
                                                  __half* __restrict__ oa,
                                                  const float* __restrict__ b,
                                                  __half* __restrict__ ob)
{
    size_t i = (size_t)blockIdx.x * 256 + threadIdx.x;
    const float* s = blockIdx.y ? b : a;
    __half* d = blockIdx.y ? ob : oa;
    float4 v = *reinterpret_cast<const float4*>(&s[i * 4]);
    uint2 u = make_uint2(packf16(v.x, v.y), packf16(v.z, v.w));
    *reinterpret_cast<uint2*>(&d[i * 4]) = u;
}

// ---------------------------------------------------------------------------
// fp16 GEMM: 128x64 block tile, 8 warps of 32x32, 3 CTA/SM.
// ldmatrix frag loads, race-safe 2-stage cp.async.
// vtrans=1: tile written transposed into vT[b][768][512] via smem staging.
// ---------------------------------------------------------------------------
struct GB { const __half* A1; const __half* A2; const __half* Wt; const float* bias;
            void* C; int K1; int K2; int half_out; int vtrans; };
struct GBatch { GB g[6]; };

__global__ __launch_bounds__(256, 3) void gemm_f16(GBatch batch)
{
    __shared__ alignas(16) uint32_t As[2][128][20];   // 20480 B
    __shared__ alignas(16) uint32_t Bs[2][64][20];    // 10240 B

    const GB gb = batch.g[blockIdx.z];
    const int tid  = threadIdx.x;
    const int lane = tid & 31;
    const int warp = tid >> 5;
    const int wm = (warp >> 1) * 32;     // 4 m-warps
    const int wn = (warp & 1) * 32;      // 2 n-warps
    const int row0 = blockIdx.y * 128;
    const int col0 = blockIdx.x * 64;
    const int K1 = gb.K1, Ktot = K1 + gb.K2;
    const int nc = Ktot >> 5;
    const int lr = lane >> 2, lc = lane & 3;

    float acc[2][4][4] = {};

    const int a_row = (lane & 7) + ((lane >> 3) & 1) * 8;
    const int a_cw  = ((lane >> 4) & 1) * 4;
    const int b_row = (lane & 7) + ((lane >> 4) & 1) * 8;
    const int b_cw  = ((lane >> 3) & 1) * 4;

    const uint32_t as0 = (uint32_t)__cvta_generic_to_shared(&As[0][0][0]);
    const uint32_t bs0 = (uint32_t)__cvta_generic_to_shared(&Bs[0][0][0]);
    const uint32_t abufsz = 128 * 20 * 4;
    const uint32_t bbufsz = 64 * 20 * 4;

    auto fill = [&](int c, int buf) {
        const int kc0 = c << 5;
        const __half* A; int kc, lda;
        if (kc0 < K1) { A = gb.A1; kc = kc0;      lda = K1; }
        else          { A = gb.A2; kc = kc0 - K1; lda = gb.K2; }
        #pragma unroll
        for (int i = 0; i < 2; i++) {
            int idx = tid + i * 256;
            int r = idx >> 2, ch = idx & 3;
            cp16(&As[buf][r][ch * 4], &A[(size_t)(row0 + r) * lda + kc + ch * 8]);
        }
        {
            int r = tid >> 2, ch = tid & 3;   // 64 rows x 4 chunks = 256
            cp16(&Bs[buf][r][ch * 4], &gb.Wt[(size_t)(col0 + r) * Ktot + kc0 + ch * 8]);
        }
    };

    fill(0, 0); CP_COMMIT();
    fill(1, 1); CP_COMMIT();

    for (int c = 0; c < nc; c++) {
        const int buf = c & 1;
        asm volatile("cp.async.wait_group 1;" ::: "memory");
        __syncthreads();

        const uint32_t asb = as0 + buf * abufsz;
        const uint32_t bsb = bs0 + buf * bbufsz;
        #pragma unroll
        for (int ks = 0; ks < 2; ks++) {
            uint32_t a[2][4], b[4][2];
            #pragma unroll
            for (int mi = 0; mi < 2; mi++) {
                uint32_t ad = asb + (((wm + mi * 16 + a_row) * 20) + ks * 8 + a_cw) * 4;
                LDSM_X4(a[mi][0], a[mi][1], a[mi][2], a[mi][3], ad);
            }
            #pragma unroll
            for (int np = 0; np < 2; np++) {
                uint32_t bd = bsb + (((wn + np * 16 + b_row) * 20) + ks * 8 + b_cw) * 4;
                LDSM_X4(b[np*2][0], b[np*2][1], b[np*2+1][0], b[np*2+1][1], bd);
            }
            #pragma unroll
            for (int mi = 0; mi < 2; mi++)
                #pragma unroll
                for (int ni = 0; ni < 4; ni++)
                    MMA_F16(acc[mi][ni], a[mi], b[ni][0], b[ni][1]);
        }
        __syncthreads();
        if (c + 2 < nc) fill(c + 2, buf);
        CP_COMMIT();
    }

    const float* bias = gb.bias;
    if (gb.vtrans) {
        // Stage transposed: stg[d_local(0..63)][s_local(0..127)], stride 136.
        __half* stg = reinterpret_cast<__half*>(&As[0][0][0]);
        __syncthreads();
        #pragma unroll
        for (int mi = 0; mi < 2; mi++)
            #pragma unroll
            for (int ni = 0; ni < 4; ni++) {
                int sl = wm + mi * 16 + lr;
                int dl = wn + ni * 8 + lc * 2;
                float b0 = bias[col0 + dl], b1 = bias[col0 + dl + 1];
                stg[(dl    ) * 136 + sl    ] = __float2half(acc[mi][ni][0] + b0);
                stg[(dl + 1) * 136 + sl    ] = __float2half(acc[mi][ni][1] + b1);
                stg[(dl    ) * 136 + sl + 8] = __float2half(acc[mi][ni][2] + b0);
                stg[(dl + 1) * 136 + sl + 8] = __float2half(acc[mi][ni][3] + b1);
            }
        __syncthreads();
        const int b  = row0 >> 9;
        const int sq = row0 & 511;
        __half* Vt = (__half*)gb.C;
        const int d  = tid >> 2;             // 0..63
        const int sh = (tid & 3) * 32;       // 0,32,64,96
        __half* dst = Vt + ((size_t)(b * DIM + col0 + d)) * SEQ + sq + sh;
        const __half* src = stg + d * 136 + sh;
        reinterpret_cast<uint4*>(dst)[0] = reinterpret_cast<const uint4*>(src)[0];
        reinterpret_cast<uint4*>(dst)[1] = reinterpret_cast<const uint4*>(src)[1];
        reinterpret_cast<uint4*>(dst)[2] = reinterpret_cast<const uint4*>(src)[2];
        reinterpret_cast<uint4*>(dst)[3] = reinterpret_cast<const uint4*>(src)[3];
    } else if (gb.half_out) {
        __half* C = (__half*)gb.C;
        #pragma unroll
        for (int mi = 0; mi < 2; mi++)
            #pragma unroll
            for (int ni = 0; ni < 4; ni++) {
                int r = row0 + wm + mi * 16 + lr;
                int cc = col0 + wn + ni * 8 + lc * 2;
                float b0 = bias[cc], b1 = bias[cc + 1];
                *reinterpret_cast<uint32_t*>(&C[(size_t)r * DIM + cc]) =
                    packf16(acc[mi][ni][0] + b0, acc[mi][ni][1] + b1);
                *reinterpret_cast<uint32_t*>(&C[(size_t)(r + 8) * DIM + cc]) =
                    packf16(acc[mi][ni][2] + b0, acc[mi][ni][3] + b1);
            }
    } else {
        float* C = (float*)gb.C;
        #pragma unroll
        for (int mi = 0; mi < 2; mi++)
            #pragma unroll
            for (int ni = 0; ni < 4; ni++) {
                int r = row0 + wm + mi * 16 + lr;
                int cc = col0 + wn + ni * 8 + lc * 2;
                float b0 = bias[cc], b1 = bias[cc + 1];
                *reinterpret_cast<float2*>(&C[(size_t)r * DIM + cc]) =
                    make_float2(acc[mi][ni][0] + b0, acc[mi][ni][1] + b1);
                *reinterpret_cast<float2*>(&C[(size_t)(r + 8) * DIM + cc]) =
                    make_float2(acc[mi][ni][2] + b0, acc[mi][ni][3] + b1);
            }
    }
}

// ---------------------------------------------------------------------------
// fp16 merged dual-attention (R14 config, measured 92.7us): 16-row warp
// M-tile, ldmatrix, unshifted softmax, 2-stage race-safe cp.async, 2 CTA/SM.
// ---------------------------------------------------------------------------
struct AttnJob { const __half* Q1; const __half* Q2; const __half* K;
                 const __half* Vt; __half* O1; __half* O2; };
struct AttnBatch2 { AttnJob j[2]; };

__global__ __launch_bounds__(256, 2) void attn_f16(AttnBatch2 batch)
{
    __shared__ uint32_t Ks[2][64][36];
    __shared__ uint32_t VT[2][64][36];

    const int tid  = threadIdx.x;
    const int lane = tid & 31;
    const int warp = tid >> 5;
    const int qset = warp >> 2;
    const int wq   = (warp & 3) * 16;
    const int lr = lane >> 2, lc = lane & 3;

    const int qt = blockIdx.x;               // 0..7
    const int h  = blockIdx.y;
    const int b  = blockIdx.z & 7;
    const AttnJob J = batch.j[blockIdx.z >> 3];

    const __half* Qg = (qset == 0 ? J.Q1 : J.Q2)
                       + ((size_t)(b * SEQ + qt * 64)) * DIM + h * DHEAD;
    const __half* Kg = J.K + (size_t)b * SEQ * DIM + h * DHEAD;
    const __half* Vg = J.Vt + ((size_t)(b * DIM + h * DHEAD)) * SEQ;
    __half* Og = (qset == 0 ? J.O1 : J.O2);

    auto issue_kv = [&](int kt, int buf) {
        #pragma unroll
        for (int i = 0; i < 2; i++) {
            int idx = tid + i * 256;
            int r = idx >> 3, ch = idx & 7;
            cp16(&Ks[buf][r][ch * 4], &Kg[(size_t)(kt * 64 + r) * DIM + ch * 8]);
        }
        #pragma unroll
        for (int i = 0; i < 2; i++) {
            int idx = tid + i * 256;
            int r = idx >> 3, ch = idx & 7;
            cp16(&VT[buf][r][ch * 4], &Vg[(size_t)r * SEQ + kt * 64 + ch * 8]);
        }
    };

    issue_kv(0, 0); CP_COMMIT();
    issue_kv(1, 1); CP_COMMIT();

    uint32_t qa[4][4];
    #pragma unroll
    for (int kk = 0; kk < 4; kk++) {
        qa[kk][0] = *reinterpret_cast<const uint32_t*>(&Qg[(size_t)(wq + lr    ) * DIM + kk * 16 + 2 * lc    ]);
        qa[kk][1] = *reinterpret_cast<const uint32_t*>(&Qg[(size_t)(wq + lr + 8) * DIM + kk * 16 + 2 * lc    ]);
        qa[kk][2] = *reinterpret_cast<const uint32_t*>(&Qg[(size_t)(wq + lr    ) * DIM + kk * 16 + 2 * lc + 8]);
        qa[kk][3] = *reinterpret_cast<const uint32_t*>(&Qg[(size_t)(wq + lr + 8) * DIM + kk * 16 + 2 * lc + 8]);
    }

    const int b_row = (lane & 7) + ((lane >> 4) & 1) * 8;
    const int b_cw  = ((lane >> 3) & 1) * 4;
    const uint32_t ks0 = (uint32_t)__cvta_generic_to_shared(&Ks[0][0][0]);
    const uint32_t vt0 = (uint32_t)__cvta_generic_to_shared(&VT[0][0][0]);
    const uint32_t bufsz = 64 * 36 * 4;

    float o[8][4] = {};
    float l0v = 0.f, l1v = 0.f;
    const float Cs = 0.1803368801f;   // 0.125 * log2(e)

    for (int kt = 0; kt < 8; kt++) {
        const int buf = kt & 1;
        asm volatile("cp.async.wait_group 1;" ::: "memory");
        __syncthreads();

        const uint32_t ksb = ks0 + buf * bufsz;
        const uint32_t vtb = vt0 + buf * bufsz;

        // S = Q @ K^T
        float sc[8][4] = {};
        #pragma unroll
        for (int kk = 0; kk < 4; kk++)
            #pragma unroll
            for (int np = 0; np < 4; np++) {
                uint32_t t0, t1, t2, t3;
                uint32_t ad = ksb + (((np * 16 + b_row) * 36) + kk * 8 + b_cw) * 4;
                LDSM_X4(t0, t1, t2, t3, ad);
                MMA_F16(sc[np * 2    ], qa[kk], t0, t1);
                MMA_F16(sc[np * 2 + 1], qa[kk], t2, t3);
            }

        // Unshifted softmax exp (f16x2)
        uint32_t pe[8][2];
        float s0f = 0.f, s1f = 0.f;
        #pragma unroll
        for (int ni = 0; ni < 8; ni++) {
            uint32_t h01 = packf16(sc[ni][0] * Cs, sc[ni][1] * Cs);
            uint32_t h23 = packf16(sc[ni][2] * Cs, sc[ni][3] * Cs);
            uint32_t e01, e23;
            asm("ex2.approx.f16x2 %0, %1;" : "=r"(e01) : "r"(h01));
            asm("ex2.approx.f16x2 %0, %1;" : "=r"(e23) : "r"(h23));
            pe[ni][0] = e01;
            pe[ni][1] = e23;
            float2 f01 = __half22float2(*reinterpret_cast<__half2*>(&e01));
            float2 f23 = __half22float2(*reinterpret_cast<__half2*>(&e23));
            s0f += f01.x + f01.y;
            s1f += f23.x + f23.y;
        }
        l0v += s0f;
        l1v += s1f;

        // O += P @ V
        #pragma unroll
        for (int kk = 0; kk < 4; kk++) {
            uint32_t pa[4];
            pa[0] = pe[2 * kk    ][0];
            pa[1] = pe[2 * kk    ][1];
            pa[2] = pe[2 * kk + 1][0];
            pa[3] = pe[2 * kk + 1][1];
            #pragma unroll
            for (int np = 0; np < 4; np++) {
                uint32_t t0, t1, t2, t3;
                uint32_t ad = vtb + (((np * 16 + b_row) * 36) + kk * 8 + b_cw) * 4;
                LDSM_X4(t0, t1, t2, t3, ad);
                MMA_F16(o[np * 2    ], pa, t0, t1);
                MMA_F16(o[np * 2 + 1], pa, t2, t3);
            }
        }
        __syncthreads();
        if (kt + 2 < 8) issue_kv(kt + 2, buf);
        CP_COMMIT();
    }

    l0v += __shfl_xor_sync(0xffffffffu, l0v, 1);
    l0v += __shfl_xor_sync(0xffffffffu, l0v, 2);
    l1v += __shfl_xor_sync(0xffffffffu, l1v, 1);
    l1v += __shfl_xor_sync(0xffffffffu, l1v, 2);

    float inv0 = 1.f / l0v, inv1 = 1.f / l1v;
    #pragma unroll
    for (int ni = 0; ni < 8; ni++) {
        size_t base = ((size_t)(b * SEQ + qt * 64 + wq + lr)) * DIM
                      + h * DHEAD + ni * 8 + 2 * lc;
        *reinterpret_cast<uint32_t*>(&Og[base]) =
            packf16(o[ni][0] * inv0, o[ni][1] * inv0);
        *reinterpret_cast<uint32_t*>(&Og[base + 8 * DIM]) =
            packf16(o[ni][2] * inv1, o[ni][3] * inv1);
    }
}

// ---------------------------------------------------------------------------
// Host launcher
// ---------------------------------------------------------------------------
extern "C" void kernel_launch(void* const* d_in, const int* in_sizes, int n_in,
                              void* d_out, int out_size)
{
    const float* hs   = (const float*)d_in[0];
    const float* mol  = (const float*)d_in[1];
    const float* Wq   = (const float*)d_in[2];  const float* bq   = (const float*)d_in[3];
    const float* Wk   = (const float*)d_in[4];  const float* bk   = (const float*)d_in[5];
    const float* Wv   = (const float*)d_in[6];  const float* bv   = (const float*)d_in[7];
    const float* Wqm  = (const float*)d_in[8];  const float* bqm  = (const float*)d_in[9];
    const float* Wkm  = (const float*)d_in[10]; const float* bkm  = (const float*)d_in[11];
    const float* Wvm  = (const float*)d_in[12]; const float* bvm  = (const float*)d_in[13];
    const float* Wfc  = (const float*)d_in[14]; const float* bfc  = (const float*)d_in[15];
    const float* Wfcm = (const float*)d_in[16]; const float* bfcm = (const float*)d_in[17];
    const float* Wo   = (const float*)d_in[18]; const float* bo   = (const float*)d_in[19];
    const float* Wom  = (const float*)d_in[20]; const float* bom  = (const float*)d_in[21];

    float* outp = (float*)d_out;
    float* outm = outp + (size_t)MAT;

    float* base = nullptr;
    cudaGetSymbolAddress((void**)&base, g_scratch);
    __half* hb = (__half*)base;
    __half* q    = hb + 0ULL  * MAT;
    __half* k    = hb + 1ULL  * MAT;
    __half* qm   = hb + 3ULL  * MAT;
    __half* km   = hb + 4ULL  * MAT;
    __half* vT   = hb + 6ULL  * MAT;
    __half* vmT  = hb + 7ULL  * MAT;
    __half* app  = hb + 8ULL  * MAT;
    __half* amp  = hb + 9ULL  * MAT;
    __half* amm  = hb + 10ULL * MAT;
    __half* apm  = hb + 11ULL * MAT;
    __half* c1   = hb + 12ULL * MAT;
    __half* c2   = hb + 13ULL * MAT;
    __half* hsr  = hb + 14ULL * MAT;
    __half* molr = hb + 15ULL * MAT;
    __half* wb   = hb + 16ULL * MAT;
    __half* WqT  = wb;
    __half* WkT  = WqT  + W768;
    __half* WvT  = WkT  + W768;
    __half* WqmT = WvT  + W768;
    __half* WkmT = WqmT + W768;
    __half* WvmT = WkmT + W768;
    __half* WoT  = WvmT + W768;
    __half* WomT = WoT  + W768;
    __half* WfcT = WomT + W768;
    __half* WfcmT= WfcT + W1536;

    // 0) Pre-passes
    TBatch tb = {{
        { Wq,  WqT,  768, 768 },  { Wk,  WkT,  768, 768 },
        { Wv,  WvT,  768, 768 },  { Wqm, WqmT, 768, 768 },
        { Wkm, WkmT, 768, 768 },  { Wvm, WvmT, 768, 768 },
        { Wo,  WoT,  768, 768 },  { Wom, WomT, 768, 768 },
        { Wfc, WfcT, 1536, 768 }, { Wfcm, WfcmT, 1536, 768 },
    }};
    transpose_round<<<dim3(48, 24, 10), 256>>>(tb);
    round_copy<<<dim3(MAT / 1024, 2), 256>>>(hs, hsr, mol, molr);

    // 1) Six projections -> fp16; V projections write TRANSPOSED (fused).
    GBatch proj = {{
        { hsr,  nullptr, WqT,  bq,  q,   DIM, 0, 1, 0 },
        { hsr,  nullptr, WkT,  bk,  k,   DIM, 0, 1, 0 },
        { hsr,  nullptr, WvT,  bv,  vT,  DIM, 0, 1, 1 },
        { molr, nullptr, WqmT, bqm, qm,  DIM, 0, 1, 0 },
        { molr, nullptr, WkmT, bkm, km,  DIM, 0, 1, 0 },
        { molr, nullptr, WvmT, bvm, vmT, DIM, 0, 1, 1 },
    }};
    gemm_f16<<<dim3(DIM / 64, ROWS / 128, 6), 256>>>(proj);

    // 2) Merged dual attention (64-row q-tiles, 2 CTA/SM)
    AttnBatch2 ab = {{
        { q,  qm, k,  vT,  app, amp },
        { qm, q,  km, vmT, amm, apm },
    }};
    attn_f16<<<dim3(SEQ / 64, HEADS, 2 * BATCH), 256>>>(ab);

    // 3) Concat-FC pair (dual-A, K=1536) -> fp16
    GBatch fc = {{
        { app, amp, WfcT,  bfc,  c1, DIM, DIM, 1, 0 },
        { amm, apm, WfcmT, bfcm, c2, DIM, DIM, 1, 0 },
        {}, {}, {}, {},
    }};
    gemm_f16<<<dim3(DIM / 64, ROWS / 128, 2), 256>>>(fc);

    // 4) Output projections -> fp32
    GBatch outg = {{
        { c1, nullptr, WoT,  bo,  outp, DIM, 0, 0, 0 },
        { c2, nullptr, WomT, bom, outm, DIM, 0, 0, 0 },
        {}, {}, {}, {},
    }};
    gemm_f16<<<dim3(DIM / 64, ROWS / 128, 2), 256>>>(outg);
}

// round 17
// speedup vs baseline: 1.1430x; 1.1430x over previous
#include <cuda_runtime.h>
#include <cuda_fp16.h>
#include <cstdint>

#define BATCH 8
#define SEQ   512
#define DIM   768
#define HEADS 12
#define DHEAD 64
#define ROWS  (BATCH * SEQ)        // 4096
#define MAT   (ROWS * DIM)         // 3145728
#define W768  (768 * 768)
#define W1536 (1536 * 768)

__device__ float g_scratch[17ULL * MAT];

__device__ __forceinline__ uint32_t packf16(float lo, float hi) {
    uint32_t r;
    asm("cvt.rn.f16x2.f32 %0, %1, %2;" : "=r"(r) : "f"(hi), "f"(lo));
    return r;
}

#define MMA_F16(D, A, B0, B1)                                               \
    asm volatile(                                                           \
        "mma.sync.aligned.m16n8k16.row.col.f32.f16.f16.f32 "                \
        "{%0,%1,%2,%3}, {%4,%5,%6,%7}, {%8,%9}, {%0,%1,%2,%3};"             \
        : "+f"((D)[0]), "+f"((D)[1]), "+f"((D)[2]), "+f"((D)[3])            \
        : "r"((A)[0]), "r"((A)[1]), "r"((A)[2]), "r"((A)[3]),               \
          "r"(B0), "r"(B1))

#define LDSM_X4(R0, R1, R2, R3, ADDR)                                       \
    asm volatile("ldmatrix.sync.aligned.m8n8.x4.shared.b16 {%0,%1,%2,%3}, [%4];" \
        : "=r"(R0), "=r"(R1), "=r"(R2), "=r"(R3) : "r"(ADDR))

#define CP_COMMIT() asm volatile("cp.async.commit_group;")

__device__ __forceinline__ void cp16(void* smem_ptr, const void* gptr) {
    uint32_t saddr = (uint32_t)__cvta_generic_to_shared(smem_ptr);
    asm volatile("cp.async.ca.shared.global [%0], [%1], 16;" :: "r"(saddr), "l"(gptr));
}

// ---------------------------------------------------------------------------
// Fused pre-pass: z<10 -> weight transpose to [N,K] fp16; z>=10 -> hs/mol
// fp32->fp16 round-copy slices (bounds-guarded).
// ---------------------------------------------------------------------------
struct TJ { const float* src; __half* dst; int K; int N; };
struct TBatch { TJ j[10]; };

__global__ __launch_bounds__(256) void prepass(TBatch tb,
                                               const float* __restrict__ hs,
                                               __half* __restrict__ hsr,
                                               const float* __restrict__ mol,
                                               __half* __restrict__ molr)
{
    if (blockIdx.z >= 10) {
        // Elementwise round-copy: 6 z-slices cover 2*MAT/4 float4-groups.
        size_t e = (((size_t)(blockIdx.z - 10) * 1152) +
                    (size_t)blockIdx.y * 48 + blockIdx.x) * 256 + threadIdx.x;
        const size_t tot = 2ULL * MAT / 4;     // 1572864
        if (e >= tot) return;
        const float* s; __half* d; size_t off;
        if (e < (size_t)MAT / 4) { s = hs;  d = hsr;  off = e; }
        else                     { s = mol; d = molr; off = e - MAT / 4; }
        float4 v = *reinterpret_cast<const float4*>(&s[off * 4]);
        uint2 u = make_uint2(packf16(v.x, v.y), packf16(v.z, v.w));
        *reinterpret_cast<uint2*>(&d[off * 4]) = u;
        return;
    }

    __shared__ float t[32][33];
    const TJ J = tb.j[blockIdx.z];
    int k0 = blockIdx.x * 32, n0 = blockIdx.y * 32;
    if (k0 >= J.K || n0 >= J.N) return;
    int tx = threadIdx.x & 31, ty = threadIdx.x >> 5;
    #pragma unroll
    for (int i = 0; i < 4; i++)
        t[ty + i * 8][tx] = J.src[(size_t)(k0 + ty + i * 8) * J.N + n0 + tx];
    __syncthreads();
    #pragma unroll
    for (int i = 0; i < 4; i++)
        J.dst[(size_t)(n0 + ty + i * 8) * J.K + k0 + tx] =
            __float2half(t[tx][ty + i * 8]);
}

// ---------------------------------------------------------------------------
// fp16 GEMM (R14 config): 128x128 tile, 8 warps (2x4), ldmatrix, 2-stage
// race-safe cp.async. vtrans=1: tile written transposed into vT[b][768][512].
// ---------------------------------------------------------------------------
struct GB { const __half* A1; const __half* A2; const __half* Wt; const float* bias;
            void* C; int K1; int K2; int half_out; int vtrans; };
struct GBatch { GB g[6]; };

__global__ __launch_bounds__(256) void gemm_f16(GBatch batch)
{
    __shared__ alignas(16) uint32_t pool[2 * 2 * 128 * 20];
    typedef uint32_t Abuf[128][20];
    Abuf* As = reinterpret_cast<Abuf*>(pool);
    Abuf* Bs = reinterpret_cast<Abuf*>(pool + 2 * 128 * 20);

    const GB gb = batch.g[blockIdx.z];
    const int tid  = threadIdx.x;
    const int lane = tid & 31;
    const int warp = tid >> 5;
    const int wm = (warp >> 2) * 64;
    const int wn = (warp & 3) * 32;
    const int row0 = blockIdx.y * 128;
    const int col0 = blockIdx.x * 128;
    const int K1 = gb.K1, Ktot = K1 + gb.K2;
    const int nc = Ktot >> 5;
    const int lr = lane >> 2, lc = lane & 3;

    float acc[4][4][4] = {};

    const int a_row = (lane & 7) + ((lane >> 3) & 1) * 8;
    const int a_cw  = ((lane >> 4) & 1) * 4;
    const int b_row = (lane & 7) + ((lane >> 4) & 1) * 8;
    const int b_cw  = ((lane >> 3) & 1) * 4;

    const uint32_t as0 = (uint32_t)__cvta_generic_to_shared(pool);
    const uint32_t bufsz = 128 * 20 * 4;
    const uint32_t bs0 = as0 + 2 * bufsz;

    auto fill = [&](int c, int buf) {
        const int kc0 = c << 5;
        const __half* A; int kc, lda;
        if (kc0 < K1) { A = gb.A1; kc = kc0;      lda = K1; }
        else          { A = gb.A2; kc = kc0 - K1; lda = gb.K2; }
        #pragma unroll
        for (int i = 0; i < 2; i++) {
            int idx = tid + i * 256;
            int r = idx >> 2, ch = idx & 3;
            cp16(&As[buf][r][ch * 4], &A[(size_t)(row0 + r) * lda + kc + ch * 8]);
        }
        #pragma unroll
        for (int i = 0; i < 2; i++) {
            int idx = tid + i * 256;
            int r = idx >> 2, ch = idx & 3;
            cp16(&Bs[buf][r][ch * 4], &gb.Wt[(size_t)(col0 + r) * Ktot + kc0 + ch * 8]);
        }
    };

    fill(0, 0); CP_COMMIT();
    fill(1, 1); CP_COMMIT();

    for (int c = 0; c < nc; c++) {
        const int buf = c & 1;
        asm volatile("cp.async.wait_group 1;" ::: "memory");
        __syncthreads();

        const uint32_t asb = as0 + buf * bufsz;
        const uint32_t bsb = bs0 + buf * bufsz;
        #pragma unroll
        for (int ks = 0; ks < 2; ks++) {
            uint32_t a[4][4], b[4][2];
            #pragma unroll
            for (int mi = 0; mi < 4; mi++) {
                uint32_t ad = asb + (((wm + mi * 16 + a_row) * 20) + ks * 8 + a_cw) * 4;
                LDSM_X4(a[mi][0], a[mi][1], a[mi][2], a[mi][3], ad);
            }
            #pragma unroll
            for (int np = 0; np < 2; np++) {
                uint32_t bd = bsb + (((wn + np * 16 + b_row) * 20) + ks * 8 + b_cw) * 4;
                LDSM_X4(b[np*2][0], b[np*2][1], b[np*2+1][0], b[np*2+1][1], bd);
            }
            #pragma unroll
            for (int mi = 0; mi < 4; mi++)
                #pragma unroll
                for (int ni = 0; ni < 4; ni++)
                    MMA_F16(acc[mi][ni], a[mi], b[ni][0], b[ni][1]);
        }
        __syncthreads();
        if (c + 2 < nc) fill(c + 2, buf);
        CP_COMMIT();
    }

    const float* bias = gb.bias;
    if (gb.vtrans) {
        __half* stg = reinterpret_cast<__half*>(pool);
        __syncthreads();
        #pragma unroll
        for (int mi = 0; mi < 4; mi++)
            #pragma unroll
            for (int ni = 0; ni < 4; ni++) {
                int sl = wm + mi * 16 + lr;
                int dl = wn + ni * 8 + lc * 2;
                float b0 = bias[col0 + dl], b1 = bias[col0 + dl + 1];
                stg[(dl    ) * 136 + sl    ] = __float2half(acc[mi][ni][0] + b0);
                stg[(dl + 1) * 136 + sl    ] = __float2half(acc[mi][ni][1] + b1);
                stg[(dl    ) * 136 + sl + 8] = __float2half(acc[mi][ni][2] + b0);
                stg[(dl + 1) * 136 + sl + 8] = __float2half(acc[mi][ni][3] + b1);
            }
        __syncthreads();
        const int b  = row0 >> 9;
        const int sq = row0 & 511;
        __half* Vt = (__half*)gb.C;
        const int d  = tid >> 1;
        const int sh = (tid & 1) * 64;
        __half* dst = Vt + ((size_t)(b * DIM + col0 + d)) * SEQ + sq + sh;
        const __half* src = stg + d * 136 + sh;
        #pragma unroll
        for (int j = 0; j < 8; j++)
            reinterpret_cast<uint4*>(dst)[j] = reinterpret_cast<const uint4*>(src)[j];
    } else if (gb.half_out) {
        __half* C = (__half*)gb.C;
        #pragma unroll
        for (int mi = 0; mi < 4; mi++)
            #pragma unroll
            for (int ni = 0; ni < 4; ni++) {
                int r = row0 + wm + mi * 16 + lr;
                int cc = col0 + wn + ni * 8 + lc * 2;
                float b0 = bias[cc], b1 = bias[cc + 1];
                *reinterpret_cast<uint32_t*>(&C[(size_t)r * DIM + cc]) =
                    packf16(acc[mi][ni][0] + b0, acc[mi][ni][1] + b1);
                *reinterpret_cast<uint32_t*>(&C[(size_t)(r + 8) * DIM + cc]) =
                    packf16(acc[mi][ni][2] + b0, acc[mi][ni][3] + b1);
            }
    } else {
        float* C = (float*)gb.C;
        #pragma unroll
        for (int mi = 0; mi < 4; mi++)
            #pragma unroll
            for (int ni = 0; ni < 4; ni++) {
                int r = row0 + wm + mi * 16 + lr;
                int cc = col0 + wn + ni * 8 + lc * 2;
                float b0 = bias[cc], b1 = bias[cc + 1];
                *reinterpret_cast<float2*>(&C[(size_t)r * DIM + cc]) =
                    make_float2(acc[mi][ni][0] + b0, acc[mi][ni][1] + b1);
                *reinterpret_cast<float2*>(&C[(size_t)(r + 8) * DIM + cc]) =
                    make_float2(acc[mi][ni][2] + b0, acc[mi][ni][3] + b1);
            }
    }
}

// ---------------------------------------------------------------------------
// fp16 merged dual-attention (R14, measured 92.7us): 16-row warp M-tile,
// ldmatrix, unshifted softmax, 2-stage race-safe cp.async, 2 CTA/SM.
// ---------------------------------------------------------------------------
struct AttnJob { const __half* Q1; const __half* Q2; const __half* K;
                 const __half* Vt; __half* O1; __half* O2; };
struct AttnBatch2 { AttnJob j[2]; };

__global__ __launch_bounds__(256, 2) void attn_f16(AttnBatch2 batch)
{
    __shared__ uint32_t Ks[2][64][36];
    __shared__ uint32_t VT[2][64][36];

    const int tid  = threadIdx.x;
    const int lane = tid & 31;
    const int warp = tid >> 5;
    const int qset = warp >> 2;
    const int wq   = (warp & 3) * 16;
    const int lr = lane >> 2, lc = lane & 3;

    const int qt = blockIdx.x;               // 0..7
    const int h  = blockIdx.y;
    const int b  = blockIdx.z & 7;
    const AttnJob J = batch.j[blockIdx.z >> 3];

    const __half* Qg = (qset == 0 ? J.Q1 : J.Q2)
                       + ((size_t)(b * SEQ + qt * 64)) * DIM + h * DHEAD;
    const __half* Kg = J.K + (size_t)b * SEQ * DIM + h * DHEAD;
    const __half* Vg = J.Vt + ((size_t)(b * DIM + h * DHEAD)) * SEQ;
    __half* Og = (qset == 0 ? J.O1 : J.O2);

    auto issue_kv = [&](int kt, int buf) {
        #pragma unroll
        for (int i = 0; i < 2; i++) {
            int idx = tid + i * 256;
            int r = idx >> 3, ch = idx & 7;
            cp16(&Ks[buf][r][ch * 4], &Kg[(size_t)(kt * 64 + r) * DIM + ch * 8]);
        }
        #pragma unroll
        for (int i = 0; i < 2; i++) {
            int idx = tid + i * 256;
            int r = idx >> 3, ch = idx & 7;
            cp16(&VT[buf][r][ch * 4], &Vg[(size_t)r * SEQ + kt * 64 + ch * 8]);
        }
    };

    issue_kv(0, 0); CP_COMMIT();
    issue_kv(1, 1); CP_COMMIT();

    uint32_t qa[4][4];
    #pragma unroll
    for (int kk = 0; kk < 4; kk++) {
        qa[kk][0] = *reinterpret_cast<const uint32_t*>(&Qg[(size_t)(wq + lr    ) * DIM + kk * 16 + 2 * lc    ]);
        qa[kk][1] = *reinterpret_cast<const uint32_t*>(&Qg[(size_t)(wq + lr + 8) * DIM + kk * 16 + 2 * lc    ]);
        qa[kk][2] = *reinterpret_cast<const uint32_t*>(&Qg[(size_t)(wq + lr    ) * DIM + kk * 16 + 2 * lc + 8]);
        qa[kk][3] = *reinterpret_cast<const uint32_t*>(&Qg[(size_t)(wq + lr + 8) * DIM + kk * 16 + 2 * lc + 8]);
    }

    const int b_row = (lane & 7) + ((lane >> 4) & 1) * 8;
    const int b_cw  = ((lane >> 3) & 1) * 4;
    const uint32_t ks0 = (uint32_t)__cvta_generic_to_shared(&Ks[0][0][0]);
    const uint32_t vt0 = (uint32_t)__cvta_generic_to_shared(&VT[0][0][0]);
    const uint32_t bufsz = 64 * 36 * 4;

    float o[8][4] = {};
    float l0v = 0.f, l1v = 0.f;
    const float Cs = 0.1803368801f;   // 0.125 * log2(e)

    for (int kt = 0; kt < 8; kt++) {
        const int buf = kt & 1;
        asm volatile("cp.async.wait_group 1;" ::: "memory");
        __syncthreads();

        const uint32_t ksb = ks0 + buf * bufsz;
        const uint32_t vtb = vt0 + buf * bufsz;

        float sc[8][4] = {};
        #pragma unroll
        for (int kk = 0; kk < 4; kk++)
            #pragma unroll
            for (int np = 0; np < 4; np++) {
                uint32_t t0, t1, t2, t3;
                uint32_t ad = ksb + (((np * 16 + b_row) * 36) + kk * 8 + b_cw) * 4;
                LDSM_X4(t0, t1, t2, t3, ad);
                MMA_F16(sc[np * 2    ], qa[kk], t0, t1);
                MMA_F16(sc[np * 2 + 1], qa[kk], t2, t3);
            }

        uint32_t pe[8][2];
        float s0f = 0.f, s1f = 0.f;
        #pragma unroll
        for (int ni = 0; ni < 8; ni++) {
            uint32_t h01 = packf16(sc[ni][0] * Cs, sc[ni][1] * Cs);
            uint32_t h23 = packf16(sc[ni][2] * Cs, sc[ni][3] * Cs);
            uint32_t e01, e23;
            asm("ex2.approx.f16x2 %0, %1;" : "=r"(e01) : "r"(h01));
            asm("ex2.approx.f16x2 %0, %1;" : "=r"(e23) : "r"(h23));
            pe[ni][0] = e01;
            pe[ni][1] = e23;
            float2 f01 = __half22float2(*reinterpret_cast<__half2*>(&e01));
            float2 f23 = __half22float2(*reinterpret_cast<__half2*>(&e23));
            s0f += f01.x + f01.y;
            s1f += f23.x + f23.y;
        }
        l0v += s0f;
        l1v += s1f;

        #pragma unroll
        for (int kk = 0; kk < 4; kk++) {
            uint32_t pa[4];
            pa[0] = pe[2 * kk    ][0];
            pa[1] = pe[2 * kk    ][1];
            pa[2] = pe[2 * kk + 1][0];
            pa[3] = pe[2 * kk + 1][1];
            #pragma unroll
            for (int np = 0; np < 4; np++) {
                uint32_t t0, t1, t2, t3;
                uint32_t ad = vtb + (((np * 16 + b_row) * 36) + kk * 8 + b_cw) * 4;
                LDSM_X4(t0, t1, t2, t3, ad);
                MMA_F16(o[np * 2    ], pa, t0, t1);
                MMA_F16(o[np * 2 + 1], pa, t2, t3);
            }
        }
        __syncthreads();
        if (kt + 2 < 8) issue_kv(kt + 2, buf);
        CP_COMMIT();
    }

    l0v += __shfl_xor_sync(0xffffffffu, l0v, 1);
    l0v += __shfl_xor_sync(0xffffffffu, l0v, 2);
    l1v += __shfl_xor_sync(0xffffffffu, l1v, 1);
    l1v += __shfl_xor_sync(0xffffffffu, l1v, 2);

    float inv0 = 1.f / l0v, inv1 = 1.f / l1v;
    #pragma unroll
    for (int ni = 0; ni < 8; ni++) {
        size_t base = ((size_t)(b * SEQ + qt * 64 + wq + lr)) * DIM
                      + h * DHEAD + ni * 8 + 2 * lc;
        *reinterpret_cast<uint32_t*>(&Og[base]) =
            packf16(o[ni][0] * inv0, o[ni][1] * inv0);
        *reinterpret_cast<uint32_t*>(&Og[base + 8 * DIM]) =
            packf16(o[ni][2] * inv1, o[ni][3] * inv1);
    }
}

// ---------------------------------------------------------------------------
// Host launcher: 5 launches total.
// ---------------------------------------------------------------------------
extern "C" void kernel_launch(void* const* d_in, const int* in_sizes, int n_in,
                              void* d_out, int out_size)
{
    const float* hs   = (const float*)d_in[0];
    const float* mol  = (const float*)d_in[1];
    const float* Wq   = (const float*)d_in[2];  const float* bq   = (const float*)d_in[3];
    const float* Wk   = (const float*)d_in[4];  const float* bk   = (const float*)d_in[5];
    const float* Wv   = (const float*)d_in[6];  const float* bv   = (const float*)d_in[7];
    const float* Wqm  = (const float*)d_in[8];  const float* bqm  = (const float*)d_in[9];
    const float* Wkm  = (const float*)d_in[10]; const float* bkm  = (const float*)d_in[11];
    const float* Wvm  = (const float*)d_in[12]; const float* bvm  = (const float*)d_in[13];
    const float* Wfc  = (const float*)d_in[14]; const float* bfc  = (const float*)d_in[15];
    const float* Wfcm = (const float*)d_in[16]; const float* bfcm = (const float*)d_in[17];
    const float* Wo   = (const float*)d_in[18]; const float* bo   = (const float*)d_in[19];
    const float* Wom  = (const float*)d_in[20]; const float* bom  = (const float*)d_in[21];

    float* outp = (float*)d_out;
    float* outm = outp + (size_t)MAT;

    float* base = nullptr;
    cudaGetSymbolAddress((void**)&base, g_scratch);
    __half* hb = (__half*)base;
    __half* q    = hb + 0ULL  * MAT;
    __half* k    = hb + 1ULL  * MAT;
    __half* qm   = hb + 3ULL  * MAT;
    __half* km   = hb + 4ULL  * MAT;
    __half* vT   = hb + 6ULL  * MAT;
    __half* vmT  = hb + 7ULL  * MAT;
    __half* app  = hb + 8ULL  * MAT;
    __half* amp  = hb + 9ULL  * MAT;
    __half* amm  = hb + 10ULL * MAT;
    __half* apm  = hb + 11ULL * MAT;
    __half* c1   = hb + 12ULL * MAT;
    __half* c2   = hb + 13ULL * MAT;
    __half* hsr  = hb + 14ULL * MAT;
    __half* molr = hb + 15ULL * MAT;
    __half* wb   = hb + 16ULL * MAT;
    __half* WqT  = wb;
    __half* WkT  = WqT  + W768;
    __half* WvT  = WkT  + W768;
    __half* WqmT = WvT  + W768;
    __half* WkmT = WqmT + W768;
    __half* WvmT = WkmT + W768;
    __half* WoT  = WvmT + W768;
    __half* WomT = WoT  + W768;
    __half* WfcT = WomT + W768;
    __half* WfcmT= WfcT + W1536;

    // 0) Fused pre-pass: weight transposes (z 0-9) + hs/mol round-copy (z 10-15)
    TBatch tb = {{
        { Wq,  WqT,  768, 768 },  { Wk,  WkT,  768, 768 },
        { Wv,  WvT,  768, 768 },  { Wqm, WqmT, 768, 768 },
        { Wkm, WkmT, 768, 768 },  { Wvm, WvmT, 768, 768 },
        { Wo,  WoT,  768, 768 },  { Wom, WomT, 768, 768 },
        { Wfc, WfcT, 1536, 768 }, { Wfcm, WfcmT, 1536, 768 },
    }};
    prepass<<<dim3(48, 24, 16), 256>>>(tb, hs, hsr, mol, molr);

    // 1) Six projections -> fp16; V projections write TRANSPOSED (fused).
    GBatch proj = {{
        { hsr,  nullptr, WqT,  bq,  q,   DIM, 0, 1, 0 },
        { hsr,  nullptr, WkT,  bk,  k,   DIM, 0, 1, 0 },
        { hsr,  nullptr, WvT,  bv,  vT,  DIM, 0, 1, 1 },
        { molr, nullptr, WqmT, bqm, qm,  DIM, 0, 1, 0 },
        { molr, nullptr, WkmT, bkm, km,  DIM, 0, 1, 0 },
        { molr, nullptr, WvmT, bvm, vmT, DIM, 0, 1, 1 },
    }};
    gemm_f16<<<dim3(6, 32, 6), 256>>>(proj);

    // 2) Merged dual attention (64-row q-tiles, 2 CTA/SM)
    AttnBatch2 ab = {{
        { q,  qm, k,  vT,  app, amp },
        { qm, q,  km, vmT, amm, apm },
    }};
    attn_f16<<<dim3(SEQ / 64, HEADS, 2 * BATCH), 256>>>(ab);

    // 3) Concat-FC pair (dual-A, K=1536) -> fp16
    GBatch fc = {{
        { app, amp, WfcT,  bfc,  c1, DIM, DIM, 1, 0 },
        { amm, apm, WfcmT, bfcm, c2, DIM, DIM, 1, 0 },
        {}, {}, {}, {},
    }};
    gemm_f16<<<dim3(6, 32, 2), 256>>>(fc);

    // 4) Output projections -> fp32
    GBatch outg = {{
        { c1, nullptr, WoT,  bo,  outp, DIM, 0, 0, 0 },
        { c2, nullptr, WomT, bom, outm, DIM, 0, 0, 0 },
        {}, {}, {}, {},
    }};
    gemm_f16<<<dim3(6, 32, 2), 256>>>(outg);
}